// round 1
// baseline (speedup 1.0000x reference)
#include <cuda_runtime.h>
#include <cuda_bf16.h>

// Problem constants (from reference)
#define BATCH  16
#define MCTRL  64
#define NCTRL  64
#define LKNOT  68      // M + P + 1
#define DEG    3
#define TOUT   256     // OUT_U == OUT_V

// Scratch (no allocation allowed) — basis functions + spans, shared by u and v
// dimensions since the reference builds V from knot_u and uses identical grids.
__device__ float g_basis[BATCH][TOUT][4];
__device__ int   g_span [BATCH][TOUT];

// ---------------------------------------------------------------------------
// Kernel A: per-batch knot normalization + span find + Cox-de Boor basis.
// One block per batch, one thread per eval parameter t.
// ---------------------------------------------------------------------------
__global__ void SurfEval_basis_kernel(const float* __restrict__ knot_u)
{
    const int b   = blockIdx.x;
    const int tid = threadIdx.x;

    __shared__ float U[LKNOT];

    if (tid == 0) {
        // cumsum
        float acc = 0.f;
        const float* k = knot_u + b * LKNOT;
        for (int i = 0; i < LKNOT; i++) { acc += k[i]; U[i] = acc; }
        // normalize: (c - c[0]) / (c[-1] - c[0])
        float c0 = U[0];
        float cl = U[LKNOT - 1];
        float den = cl - c0;
        for (int i = 0; i < LKNOT; i++) U[i] = (U[i] - c0) / den;
    }
    __syncthreads();

    // t = linspace(1e-5, 1-1e-5, 256)[tid]
    const float t = (float)(1e-5 + (double)tid * ((1.0 - 2e-5) / 255.0));

    // find span: argmin (first-occurrence) over masked positive differences
    const int S = LKNOT - 2 * DEG;  // 62
    float best = 1e30f;
    int   bi   = 0;
    for (int s = 0; s < S; s++) {
        float d    = t - U[s + DEG];
        float cand = (d > 1e-8f) ? d : 1.0f;
        if (cand < best) { best = cand; bi = s; }
    }
    int span = bi + DEG;
    if (span > MCTRL - 1) span = MCTRL - 1;   // matches JAX OOB-clamp semantics

    // Cox-de Boor, degree 3
    float Nb[DEG + 1];
    Nb[0] = 1.f;
    #pragma unroll
    for (int k = 1; k <= DEG; k++) {
        float saved = 0.f;
        #pragma unroll
        for (int r = 0; r < DEG; r++) {
            if (r >= k) break;
            float K1   = U[span + r + 1];
            float K2   = U[span + 1 - k + r];
            float temp = Nb[r] / ((K1 - t) + (t - K2));
            Nb[r]  = saved + (K1 - t) * temp;
            saved  = (t - K2) * temp;
        }
        Nb[k] = saved;
    }

    g_span[b][tid] = span;
    #pragma unroll
    for (int r = 0; r < 4; r++) g_basis[b][tid][r] = Nb[r];
}

// ---------------------------------------------------------------------------
// Kernel B: surface evaluation. One block per (batch, u-row), thread = v col.
// ---------------------------------------------------------------------------
__global__ __launch_bounds__(256) void SurfEval_eval_kernel(
    const float4* __restrict__ ctrl,   // [B][64][64] float4 (x,y,z,w)
    float*        __restrict__ out)    // [B][256][256][3]
{
    const int b = blockIdx.x >> 8;
    const int i = blockIdx.x & 255;
    const int j = threadIdx.x;

    __shared__ float4 rows[4][NCTRL];     // 4 ctrl rows for this u-span
    __shared__ float  outbuf[TOUT * 3];   // staging for coalesced stores

    // u-direction basis/span for this block's row i (broadcast reads)
    const int su = g_span[b][i];
    float nu[4];
    #pragma unroll
    for (int l = 0; l < 4; l++) nu[l] = g_basis[b][i][l];

    // cooperative load of the 4 needed ctrl rows: 256 threads -> 4x64 float4
    {
        int rr = j >> 6;
        int cc = j & 63;
        rows[rr][cc] = ctrl[((b * MCTRL) + (su - 3 + rr)) * NCTRL + cc];
    }

    // v-direction basis/span for this thread's column j (registers only)
    const float4 nv4 = *reinterpret_cast<const float4*>(g_basis[b][j]);
    const float nv[4] = { nv4.x, nv4.y, nv4.z, nv4.w };
    const int sj = g_span[b][j];

    __syncthreads();

    float ax = 0.f, ay = 0.f, az = 0.f;
    #pragma unroll
    for (int l = 0; l < 4; l++) {
        float px = 0.f, py = 0.f, pz = 0.f;
        #pragma unroll
        for (int r = 0; r < 4; r++) {
            float4 c = rows[l][sj - 3 + r];
            px += nv[r] * c.x;
            py += nv[r] * c.y;
            pz += nv[r] * c.z;
        }
        ax += nu[l] * px;
        ay += nu[l] * py;
        az += nu[l] * pz;
    }

    // stage -> fully coalesced 3x256 float stores
    outbuf[j * 3 + 0] = ax;
    outbuf[j * 3 + 1] = ay;
    outbuf[j * 3 + 2] = az;
    __syncthreads();

    float* orow = out + (size_t)((b * TOUT) + i) * TOUT * 3;
    #pragma unroll
    for (int k = 0; k < 3; k++) orow[k * TOUT + j] = outbuf[k * TOUT + j];
}

// ---------------------------------------------------------------------------
// Launch. Inputs: d_in[0]=ctrl_pts [16,64,64,4] f32, d_in[1]=knot_u [16,68],
// d_in[2]=knot_v (UNUSED — reference builds V from knot_u).
// Output: [16,256,256,3] f32.
// ---------------------------------------------------------------------------
extern "C" void kernel_launch(void* const* d_in, const int* in_sizes, int n_in,
                              void* d_out, int out_size)
{
    const float*  knot_u = (const float*) d_in[1];
    const float4* ctrl   = (const float4*)d_in[0];
    float*        out    = (float*)d_out;

    SurfEval_basis_kernel<<<BATCH, TOUT>>>(knot_u);
    SurfEval_eval_kernel<<<BATCH * TOUT, TOUT>>>(ctrl, out);
}

// round 2
// speedup vs baseline: 1.6441x; 1.6441x over previous
#include <cuda_runtime.h>
#include <cuda_bf16.h>

// Problem constants (from reference)
#define BATCH  16
#define MCTRL  64
#define NCTRL  64
#define LKNOT  68      // M + P + 1
#define DEG    3
#define TOUT   256     // OUT_U == OUT_V
#define RPB    4       // u-rows per eval block

// Scratch — basis functions + spans, shared by u and v dimensions since the
// reference builds V from knot_u and uses identical parameter grids.
__device__ float4 g_basis[BATCH][TOUT];
__device__ int    g_span [BATCH][TOUT];

// ---------------------------------------------------------------------------
// Kernel A: per-batch knot normalization + span find + Cox-de Boor basis.
// One block per batch, one thread per eval parameter t.
// ---------------------------------------------------------------------------
__global__ void SurfEval_basis_kernel(const float* __restrict__ knot_u)
{
    const int b   = blockIdx.x;
    const int tid = threadIdx.x;

    __shared__ float raw[LKNOT];
    __shared__ float U[LKNOT];

    if (tid < LKNOT) raw[tid] = knot_u[b * LKNOT + tid];
    __syncthreads();

    if (tid == 0) {
        float acc = 0.f;
        #pragma unroll 4
        for (int i = 0; i < LKNOT; i++) { acc += raw[i]; U[i] = acc; }
        float c0  = U[0];
        float den = U[LKNOT - 1] - c0;
        float inv = 1.f / den;
        for (int i = 0; i < LKNOT; i++) U[i] = (U[i] - c0) * inv;
    }
    __syncthreads();

    // t = linspace(1e-5, 1-1e-5, 256)[tid]
    const float t = (float)(1e-5 + (double)tid * ((1.0 - 2e-5) / 255.0));

    // find span: first-occurrence argmin over masked positive differences
    const int S = LKNOT - 2 * DEG;  // 62
    float best = 1e30f;
    int   bi   = 0;
    #pragma unroll 8
    for (int s = 0; s < S; s++) {
        float d    = t - U[s + DEG];
        float cand = (d > 1e-8f) ? d : 1.0f;
        if (cand < best) { best = cand; bi = s; }
    }
    int span = bi + DEG;
    if (span > MCTRL - 1) span = MCTRL - 1;

    // Cox-de Boor, degree 3
    float Nb[DEG + 1];
    Nb[0] = 1.f;
    #pragma unroll
    for (int k = 1; k <= DEG; k++) {
        float saved = 0.f;
        #pragma unroll
        for (int r = 0; r < DEG; r++) {
            if (r >= k) break;
            float K1   = U[span + r + 1];
            float K2   = U[span + 1 - k + r];
            float temp = Nb[r] / ((K1 - t) + (t - K2));
            Nb[r]  = saved + (K1 - t) * temp;
            saved  = (t - K2) * temp;
        }
        Nb[k] = saved;
    }

    g_span[b][tid]  = span;
    g_basis[b][tid] = make_float4(Nb[0], Nb[1], Nb[2], Nb[3]);
}

// ---------------------------------------------------------------------------
// Kernel B: surface evaluation, factorized tensor product.
// One block per (batch, group of RPB u-rows). 256 threads.
//   Phase 1: thread t=(ri,c) computes the u-contraction for row i0+ri, col c:
//            cols[ri][c] = sum_l nu[l] * ctrl[b][su-3+l][c]   (xyz only)
//   Phase 2: thread j contracts v: out = sum_r nv[r] * cols[ri][sj-3+r]
//   Phase 3: contiguous RPB*256*3 floats emitted as coalesced float4 stores.
// ---------------------------------------------------------------------------
__global__ __launch_bounds__(256) void SurfEval_eval_kernel(
    const float4* __restrict__ ctrl,   // [B][64][64] float4 (x,y,z,w)
    float*        __restrict__ out)    // [B][256][256][3]
{
    const int b   = blockIdx.x / (TOUT / RPB);
    const int i0  = (blockIdx.x % (TOUT / RPB)) * RPB;
    const int tid = threadIdx.x;

    __shared__ float colsx[RPB][NCTRL];
    __shared__ float colsy[RPB][NCTRL];
    __shared__ float colsz[RPB][NCTRL];
    __shared__ __align__(16) float stage[RPB * TOUT * 3];   // 12 KB

    // ---- Phase 1: u-contraction per (row, column) ----
    {
        const int ri = tid >> 6;         // 0..3
        const int c  = tid & 63;         // 0..63
        const int i  = i0 + ri;
        const int su = g_span[b][i];
        const float4 nu = g_basis[b][i];

        const float4* cp = ctrl + ((size_t)(b * MCTRL) + (su - 3)) * NCTRL + c;
        float4 p0 = cp[0 * NCTRL];
        float4 p1 = cp[1 * NCTRL];
        float4 p2 = cp[2 * NCTRL];
        float4 p3 = cp[3 * NCTRL];

        colsx[ri][c] = nu.x * p0.x + nu.y * p1.x + nu.z * p2.x + nu.w * p3.x;
        colsy[ri][c] = nu.x * p0.y + nu.y * p1.y + nu.z * p2.y + nu.w * p3.y;
        colsz[ri][c] = nu.x * p0.z + nu.y * p1.z + nu.z * p2.z + nu.w * p3.z;
    }

    // v-basis for this thread's output column (registers, reused RPB times)
    const int j = tid;
    const float4 nv = g_basis[b][j];
    const int sj = g_span[b][j] - 3;

    __syncthreads();

    // ---- Phase 2: v-contraction, RPB rows ----
    #pragma unroll
    for (int ri = 0; ri < RPB; ri++) {
        float x = nv.x * colsx[ri][sj]     + nv.y * colsx[ri][sj + 1]
                + nv.z * colsx[ri][sj + 2] + nv.w * colsx[ri][sj + 3];
        float y = nv.x * colsy[ri][sj]     + nv.y * colsy[ri][sj + 1]
                + nv.z * colsy[ri][sj + 2] + nv.w * colsy[ri][sj + 3];
        float z = nv.x * colsz[ri][sj]     + nv.y * colsz[ri][sj + 1]
                + nv.z * colsz[ri][sj + 2] + nv.w * colsz[ri][sj + 3];
        stage[(ri * TOUT + j) * 3 + 0] = x;
        stage[(ri * TOUT + j) * 3 + 1] = y;
        stage[(ri * TOUT + j) * 3 + 2] = z;
    }

    __syncthreads();

    // ---- Phase 3: coalesced float4 stores of the contiguous block chunk ----
    const float4* s4 = reinterpret_cast<const float4*>(stage);
    float4* o4 = reinterpret_cast<float4*>(out + (size_t)(b * TOUT + i0) * TOUT * 3);
    #pragma unroll
    for (int k = 0; k < RPB * TOUT * 3 / 4 / 256; k++)   // 3 iters
        o4[k * 256 + tid] = s4[k * 256 + tid];
}

// ---------------------------------------------------------------------------
// Launch. Inputs: d_in[0]=ctrl_pts [16,64,64,4] f32, d_in[1]=knot_u [16,68],
// d_in[2]=knot_v (UNUSED — reference builds V from knot_u).
// Output: [16,256,256,3] f32.
// ---------------------------------------------------------------------------
extern "C" void kernel_launch(void* const* d_in, const int* in_sizes, int n_in,
                              void* d_out, int out_size)
{
    const float*  knot_u = (const float*) d_in[1];
    const float4* ctrl   = (const float4*)d_in[0];
    float*        out    = (float*)d_out;

    SurfEval_basis_kernel<<<BATCH, TOUT>>>(knot_u);
    SurfEval_eval_kernel<<<BATCH * (TOUT / RPB), TOUT>>>(ctrl, out);
}